// round 11
// baseline (speedup 1.0000x reference)
#include <cuda_runtime.h>
#include <math.h>
#include <stdint.h>

#define DIM   1024
#define HEADS 16
#define BSZ   2
#define SEQ   2048
#define HD    64
#define ROWS  (BSZ*SEQ)   // 4096

// Scratch (device globals; allocation-free)
__device__ float g_qkv[(size_t)ROWS * 3 * DIM];
__device__ float g_attn[(size_t)ROWS * DIM];
__device__ float g_hid[(size_t)ROWS * 2 * DIM];
// tf32-rounded copies of inputs (weights stored TRANSPOSED [N][K])
__device__ float g_seq_t[(size_t)ROWS * DIM];
__device__ float g_wqkv_t[(size_t)DIM * 3 * DIM];
__device__ float g_w1_t[(size_t)DIM * 2 * DIM];
__device__ float g_w2_t[(size_t)2 * DIM * DIM];

// ---------------------------------------------------------------------------
// helpers
// ---------------------------------------------------------------------------
__device__ __forceinline__ void cp16(void* smem_dst, const void* gmem_src) {
    uint32_t d = (uint32_t)__cvta_generic_to_shared(smem_dst);
    asm volatile("cp.async.cg.shared.global [%0], [%1], 16;\n" :: "r"(d), "l"(gmem_src));
}
#define CP_COMMIT() asm volatile("cp.async.commit_group;\n" ::: "memory")
#define CP_WAIT1()  asm volatile("cp.async.wait_group 1;\n" ::: "memory")

__device__ __forceinline__ float f2tf32f(float x) {
    uint32_t r;
    asm("cvt.rna.tf32.f32 %0, %1;" : "=r"(r) : "f"(x));
    return __uint_as_float(r);
}

__device__ __forceinline__ float fexp2(float x) {
    float y;
    asm("ex2.approx.ftz.f32 %0, %1;" : "=f"(y) : "f"(x));
    return y;
}

__device__ __forceinline__ void mma_tf32(float c[4], const uint32_t a[4], const uint32_t* b) {
    asm volatile(
        "mma.sync.aligned.m16n8k8.row.col.f32.tf32.tf32.f32 "
        "{%0,%1,%2,%3}, {%4,%5,%6,%7}, {%8,%9}, {%0,%1,%2,%3};\n"
        : "+f"(c[0]), "+f"(c[1]), "+f"(c[2]), "+f"(c[3])
        : "r"(a[0]), "r"(a[1]), "r"(a[2]), "r"(a[3]), "r"(b[0]), "r"(b[1]));
}

__device__ __forceinline__ void ldsm_x4(uint32_t r[4], uint32_t addr) {
    asm volatile("ldmatrix.sync.aligned.m8n8.x4.shared.b16 {%0,%1,%2,%3}, [%4];"
                 : "=r"(r[0]), "=r"(r[1]), "=r"(r[2]), "=r"(r[3]) : "r"(addr));
}

// ---------------------------------------------------------------------------
// tf32 rounding pre-pass: elementwise (seq) + transpose (weights)
// ---------------------------------------------------------------------------
__global__ __launch_bounds__(256)
void cvt_tf32_kernel(const float* __restrict__ src, float* __restrict__ dst)
{
    size_t i = ((size_t)blockIdx.x * 256 + threadIdx.x) * 4;
    float4 v = *(const float4*)(src + i);
    v.x = f2tf32f(v.x); v.y = f2tf32f(v.y);
    v.z = f2tf32f(v.z); v.w = f2tf32f(v.w);
    *(float4*)(dst + i) = v;
}

// src[K][N] row-major -> dst[N][K] row-major, tf32-rounded. K,N multiples of 32.
__global__ __launch_bounds__(256)
void cvt_T_kernel(const float* __restrict__ src, float* __restrict__ dst, int K, int N)
{
    __shared__ float tile[32][33];
    const int n0 = blockIdx.x * 32, k0 = blockIdx.y * 32;
    const int tx = threadIdx.x & 31, ty4 = (threadIdx.x >> 5) * 4;
    #pragma unroll
    for (int i = 0; i < 4; i++)
        tile[ty4 + i][tx] = f2tf32f(src[(size_t)(k0 + ty4 + i) * N + n0 + tx]);
    __syncthreads();
    #pragma unroll
    for (int i = 0; i < 4; i++)
        dst[(size_t)(n0 + ty4 + i) * K + k0 + tx] = tile[tx][ty4 + i];
}

// ---------------------------------------------------------------------------
// tf32 tensor-core GEMM, both operands via ldmatrix.x4.
// A[M][K] row-major; Bt[N][K] row-major (pre-transposed weights).
// ---------------------------------------------------------------------------
#define GS 36
#define G_STAGE (128 * GS)          // 4608 floats, same for A and B
#define GEMM_SMEM_BYTES (6 * G_STAGE * 4)  // 110592

__device__ __forceinline__ void gemm_load_tile(
    const float* __restrict__ A, const float* __restrict__ Bt,
    int K, int bm, int bn, int k0,
    float* Asb, float* Bsb, int tid)
{
    #pragma unroll
    for (int i = 0; i < 4; i++) {
        int id = tid + i * 256;
        int r = id >> 3, q = (id & 7) * 4;
        cp16(Asb + r * GS + q, A  + (size_t)(bm + r) * K + k0 + q);
        cp16(Bsb + r * GS + q, Bt + (size_t)(bn + r) * K + k0 + q);
    }
}

template<int ACT, int ROUND>
__global__ __launch_bounds__(256, 2)
void tgemm_kernel(const float* __restrict__ A, const float* __restrict__ Bt,
                  const float* __restrict__ bias, float* __restrict__ C,
                  int M, int N, int K)
{
    extern __shared__ float smem[];
    float* As = smem;
    float* Bs = smem + 3 * G_STAGE;

    const int tid  = threadIdx.x;
    const int lane = tid & 31;
    const int wid  = tid >> 5;
    const int gid  = lane >> 2;
    const int tig  = lane & 3;
    const int warp_m = wid & 1;
    const int warp_n = wid >> 1;
    const int bm = blockIdx.y * 128;
    const int bn = blockIdx.x * 128;

    const int lf = lane >> 3, lr = lane & 7;
    const uint32_t As_u32 = (uint32_t)__cvta_generic_to_shared(As);
    const uint32_t Bs_u32 = (uint32_t)__cvta_generic_to_shared(Bs);
    // A-style x4: row = base + (f&1)*8 + r, col = (f>>1)*4
    const uint32_t aldm = As_u32 +
        (uint32_t)(((warp_m * 64 + (lf & 1) * 8 + lr) * GS + (lf >> 1) * 4) * 4);
    // B-style x4 (two n-tiles): row = base + (f>>1)*8 + r, col = (f&1)*4
    const uint32_t bldm = Bs_u32 +
        (uint32_t)(((warp_n * 32 + (lf >> 1) * 8 + lr) * GS + (lf & 1) * 4) * 4);

    float acc[4][4][4];
    #pragma unroll
    for (int mt = 0; mt < 4; mt++)
        #pragma unroll
        for (int nt = 0; nt < 4; nt++)
            #pragma unroll
            for (int r = 0; r < 4; r++) acc[mt][nt][r] = 0.f;

    const int T = K / 32;
    gemm_load_tile(A, Bt, K, bm, bn, 0,  As,           Bs,           tid); CP_COMMIT();
    gemm_load_tile(A, Bt, K, bm, bn, 32, As + G_STAGE, Bs + G_STAGE, tid); CP_COMMIT();

    for (int t = 0; t < T; t++) {
        CP_WAIT1();
        __syncthreads();

        int tn = t + 2;
        if (tn < T) {
            gemm_load_tile(A, Bt, K, bm, bn, tn * 32,
                           As + (tn % 3) * G_STAGE, Bs + (tn % 3) * G_STAGE, tid);
        }
        CP_COMMIT();

        const uint32_t a_stage = aldm + (uint32_t)((t % 3) * G_STAGE * 4);
        const uint32_t b_stage = bldm + (uint32_t)((t % 3) * G_STAGE * 4);

        #pragma unroll
        for (int kq = 0; kq < 4; kq++) {
            const int k0s = kq * 8;
            uint32_t af[4][4];
            #pragma unroll
            for (int mt = 0; mt < 4; mt++)
                ldsm_x4(af[mt], a_stage + (uint32_t)((mt * 16 * GS + k0s) * 4));

            uint32_t bf0[4], bf1[4];
            ldsm_x4(bf0, b_stage + (uint32_t)(k0s * 4));
            ldsm_x4(bf1, b_stage + (uint32_t)((16 * GS + k0s) * 4));

            #pragma unroll
            for (int mt = 0; mt < 4; mt++) {
                mma_tf32(acc[mt][0], af[mt], bf0);
                mma_tf32(acc[mt][1], af[mt], bf0 + 2);
                mma_tf32(acc[mt][2], af[mt], bf1);
                mma_tf32(acc[mt][3], af[mt], bf1 + 2);
            }
        }
    }

    #pragma unroll
    for (int mt = 0; mt < 4; mt++) {
        const int r0 = bm + warp_m * 64 + mt * 16 + gid;
        #pragma unroll
        for (int nt = 0; nt < 4; nt++) {
            const int c0 = bn + warp_n * 32 + nt * 8 + tig * 2;
            float b0 = 0.f, b1 = 0.f;
            if (bias) { b0 = bias[c0]; b1 = bias[c0 + 1]; }
            float v0 = acc[mt][nt][0] + b0;
            float v1 = acc[mt][nt][1] + b1;
            float v2 = acc[mt][nt][2] + b0;
            float v3 = acc[mt][nt][3] + b1;
            if (ACT == 1) {
                v0 = v0 / (1.f + __expf(-v0));
                v1 = v1 / (1.f + __expf(-v1));
                v2 = v2 / (1.f + __expf(-v2));
                v3 = v3 / (1.f + __expf(-v3));
            }
            if (ROUND) {
                v0 = f2tf32f(v0); v1 = f2tf32f(v1);
                v2 = f2tf32f(v2); v3 = f2tf32f(v3);
            }
            *(float2*)(C + (size_t)r0 * N + c0)       = make_float2(v0, v1);
            *(float2*)(C + (size_t)(r0 + 8) * N + c0) = make_float2(v2, v3);
        }
    }
}

// ---------------------------------------------------------------------------
// tf32 tensor-core flash attention. V transposed in-smem each tile so the
// PV phase uses ldmatrix.x4 exactly like the S phase.
// ---------------------------------------------------------------------------
#define ATS 68
#define KV_STAGE (2 * 64 * ATS)
#define ATTN_SMEM_FLOATS (128 * ATS + 2 * KV_STAGE)
#define ATTN_SMEM_BYTES  (ATTN_SMEM_FLOATS * 4)   // 104448

#define L2E       1.44269504f
#define SCALE_L2E (0.125f * 1.44269504f)

__device__ __forceinline__ void attn_load_kv(
    const float* kbase, const float* vbase, int kv0,
    float* Kst, float* Vst, int tid)
{
    #pragma unroll
    for (int i = 0; i < 4; i++) {
        int c = tid + i * 256;
        int r = c >> 4, q = (c & 15) * 4;
        cp16(Kst + r * ATS + q, kbase + (size_t)(kv0 + r) * (3 * DIM) + q);
        cp16(Vst + r * ATS + q, vbase + (size_t)(kv0 + r) * (3 * DIM) + q);
    }
}

__global__ __launch_bounds__(256, 2)
void attn_kernel(const float* __restrict__ qkv,
                 const float* __restrict__ mask,
                 float* __restrict__ out)
{
    extern __shared__ float smem[];
    float* Ps = smem;                 // 128 x 68 : Q staging, then P
    float* KV = smem + 128 * ATS;     // 2 stages of (K 64x68 + V 64x68)

    const int tid  = threadIdx.x;
    const int lane = tid & 31;
    const int w    = tid >> 5;
    const int gid  = lane >> 2;
    const int tig  = lane & 3;
    const int bb = blockIdx.z, h = blockIdx.y;
    const int q0 = blockIdx.x * 128;
    const size_t ldq = 3 * DIM;

    const float* qbase = qkv + (size_t)(bb * SEQ + q0) * ldq + h * HD;
    const float* kbase = qkv + (size_t)(bb * SEQ) * ldq + DIM + h * HD;
    const float* vbase = kbase + DIM;

    const int lf = lane >> 3, lr = lane & 7;
    const uint32_t Ps_u32 = (uint32_t)__cvta_generic_to_shared(Ps);
    const uint32_t KV_u32 = (uint32_t)__cvta_generic_to_shared(KV);
    const uint32_t pldm = Ps_u32 +
        (uint32_t)(((w * 16 + (lf & 1) * 8 + lr) * ATS + (lf >> 1) * 4) * 4);
    const uint32_t bldm_off =
        (uint32_t)((((lf >> 1) * 8 + lr) * ATS + (lf & 1) * 4) * 4);

    // transpose role: thread handles column d, kv block [16*tkq, 16*tkq+16)
    const int t_d  = tid & 63;
    const int t_kq = tid >> 6;

    #pragma unroll
    for (int i = 0; i < 8; i++) {
        int c = tid + i * 256;
        int r = c >> 4, q = (c & 15) * 4;
        cp16(Ps + r * ATS + q, qbase + (size_t)r * ldq + q);
    }
    attn_load_kv(kbase, vbase, 0, KV, KV + 64 * ATS, tid);
    CP_COMMIT();

    uint32_t qf[8][4];
    float oacc[8][4];
    #pragma unroll
    for (int nt = 0; nt < 8; nt++)
        #pragma unroll
        for (int r = 0; r < 4; r++) oacc[nt][r] = 0.f;
    float mrow0 = -1e30f, mrow1 = -1e30f, lrow0 = 0.f, lrow1 = 0.f;

    const int qrow = w * 16 + gid;
    const int Rg = q0 + qrow;

    const int NT = SEQ / 64;
    for (int t = 0; t < NT; t++) {
        const int cur = t & 1;
        if (t + 1 < NT) {
            float* Kn = KV + ((t + 1) & 1) * KV_STAGE;
            attn_load_kv(kbase, vbase, (t + 1) * 64, Kn, Kn + 64 * ATS, tid);
        }
        CP_COMMIT();
        CP_WAIT1();
        __syncthreads();                       // (A) stage cur ready

        // ---- in-place V transpose: V[kv][d] -> Vt[d][kv] ----
        float* vstage = KV + cur * KV_STAGE + 64 * ATS;
        float vr[16];
        #pragma unroll
        for (int q = 0; q < 4; q++)
            #pragma unroll
            for (int i = 0; i < 4; i++)
                vr[q * 4 + i] = vstage[(t_kq * 16 + q * 4 + i) * ATS + t_d];
        __syncthreads();                       // (B) all reads done
        #pragma unroll
        for (int q = 0; q < 4; q++)
            *(float4*)(vstage + t_d * ATS + t_kq * 16 + q * 4) =
                make_float4(vr[q * 4], vr[q * 4 + 1], vr[q * 4 + 2], vr[q * 4 + 3]);

        if (t == 0) {
            #pragma unroll
            for (int kt = 0; kt < 8; kt++)
                ldsm_x4(qf[kt], pldm + (uint32_t)(kt * 8 * 4));
        }

        const uint32_t kst_u32 = KV_u32 + (uint32_t)(cur * KV_STAGE * 4) + bldm_off;
        const uint32_t vst_u32 = kst_u32 + (uint32_t)(64 * ATS * 4);
        const int kv0 = t * 64;

        float sa[8][4];
        #pragma unroll
        for (int nt = 0; nt < 8; nt++)
            #pragma unroll
            for (int r = 0; r < 4; r++) sa[nt][r] = 0.f;

        // S = Q K^T
        #pragma unroll
        for (int kt = 0; kt < 8; kt++) {
            #pragma unroll
            for (int np = 0; np < 4; np++) {
                uint32_t bfr4[4];
                ldsm_x4(bfr4, kst_u32 + (uint32_t)((np * 16 * ATS + kt * 8) * 4));
                mma_tf32(sa[2 * np],     qf[kt], bfr4);
                mma_tf32(sa[2 * np + 1], qf[kt], bfr4 + 2);
            }
        }

        // scale + mask, log2 domain
        const float* mp0 = mask + (size_t)Rg * SEQ + kv0 + 2 * tig;
        const float* mp1 = mp0 + 8 * SEQ;
        #pragma unroll
        for (int nt = 0; nt < 8; nt++) {
            float2 mk0 = *(const float2*)(mp0 + nt * 8);
            float2 mk1 = *(const float2*)(mp1 + nt * 8);
            sa[nt][0] = fmaf(sa[nt][0], SCALE_L2E, mk0.x * L2E);
            sa[nt][1] = fmaf(sa[nt][1], SCALE_L2E, mk0.y * L2E);
            sa[nt][2] = fmaf(sa[nt][2], SCALE_L2E, mk1.x * L2E);
            sa[nt][3] = fmaf(sa[nt][3], SCALE_L2E, mk1.y * L2E);
        }

        float mx0 = -1e30f, mx1 = -1e30f;
        #pragma unroll
        for (int nt = 0; nt < 8; nt++) {
            mx0 = fmaxf(mx0, fmaxf(sa[nt][0], sa[nt][1]));
            mx1 = fmaxf(mx1, fmaxf(sa[nt][2], sa[nt][3]));
        }
        mx0 = fmaxf(mx0, __shfl_xor_sync(0xffffffffu, mx0, 1));
        mx0 = fmaxf(mx0, __shfl_xor_sync(0xffffffffu, mx0, 2));
        mx1 = fmaxf(mx1, __shfl_xor_sync(0xffffffffu, mx1, 1));
        mx1 = fmaxf(mx1, __shfl_xor_sync(0xffffffffu, mx1, 2));

        float mn0 = fmaxf(mrow0, mx0);
        float mn1 = fmaxf(mrow1, mx1);
        float alpha0 = fexp2(mrow0 - mn0);
        float alpha1 = fexp2(mrow1 - mn1);
        mrow0 = mn0; mrow1 = mn1;

        float s0a = 0.f, s0b = 0.f, s1a = 0.f, s1b = 0.f;
        #pragma unroll
        for (int nt = 0; nt < 8; nt++) {
            sa[nt][0] = fexp2(sa[nt][0] - mn0);
            sa[nt][1] = fexp2(sa[nt][1] - mn0);
            sa[nt][2] = fexp2(sa[nt][2] - mn1);
            sa[nt][3] = fexp2(sa[nt][3] - mn1);
            if (nt & 1) { s0b += sa[nt][0] + sa[nt][1]; s1b += sa[nt][2] + sa[nt][3]; }
            else        { s0a += sa[nt][0] + sa[nt][1]; s1a += sa[nt][2] + sa[nt][3]; }
        }
        float sum0 = s0a + s0b, sum1 = s1a + s1b;
        sum0 += __shfl_xor_sync(0xffffffffu, sum0, 1);
        sum0 += __shfl_xor_sync(0xffffffffu, sum0, 2);
        sum1 += __shfl_xor_sync(0xffffffffu, sum1, 1);
        sum1 += __shfl_xor_sync(0xffffffffu, sum1, 2);
        lrow0 = lrow0 * alpha0 + sum0;
        lrow1 = lrow1 * alpha1 + sum1;

        #pragma unroll
        for (int nt = 0; nt < 8; nt++) {
            oacc[nt][0] *= alpha0;
            oacc[nt][1] *= alpha0;
            oacc[nt][2] *= alpha1;
            oacc[nt][3] *= alpha1;
        }

        float* pr0 = Ps + qrow * ATS + 2 * tig;
        float* pr1 = pr0 + 8 * ATS;
        #pragma unroll
        for (int nt = 0; nt < 8; nt++) {
            *(float2*)(pr0 + nt * 8) = make_float2(f2tf32f(sa[nt][0]), f2tf32f(sa[nt][1]));
            *(float2*)(pr1 + nt * 8) = make_float2(f2tf32f(sa[nt][2]), f2tf32f(sa[nt][3]));
        }
        __syncthreads();                       // (C) P + Vt visible

        // O += P V  (both operands via ldmatrix.x4)
        #pragma unroll
        for (int kt = 0; kt < 8; kt++) {
            uint32_t pf[4];
            ldsm_x4(pf, pldm + (uint32_t)(kt * 8 * 4));
            #pragma unroll
            for (int np = 0; np < 4; np++) {
                uint32_t bfr4[4];
                ldsm_x4(bfr4, vst_u32 + (uint32_t)((np * 16 * ATS + kt * 8) * 4));
                mma_tf32(oacc[2 * np],     pf, bfr4);
                mma_tf32(oacc[2 * np + 1], pf, bfr4 + 2);
            }
        }
        __syncthreads();                       // (D) guard stage reuse
    }

    float inv0 = 1.f / lrow0, inv1 = 1.f / lrow1;
    float* o0 = out + (size_t)(bb * SEQ + Rg) * DIM + h * HD + 2 * tig;
    float* o1 = o0 + 8 * DIM;
    #pragma unroll
    for (int nt = 0; nt < 8; nt++) {
        *(float2*)(o0 + nt * 8) = make_float2(f2tf32f(oacc[nt][0] * inv0),
                                              f2tf32f(oacc[nt][1] * inv0));
        *(float2*)(o1 + nt * 8) = make_float2(f2tf32f(oacc[nt][2] * inv1),
                                              f2tf32f(oacc[nt][3] * inv1));
    }
}

// ---------------------------------------------------------------------------
// Launch
// ---------------------------------------------------------------------------
extern "C" void kernel_launch(void* const* d_in, const int* in_sizes, int n_in,
                              void* d_out, int out_size)
{
    const float* seq   = (const float*)d_in[0];
    const float* amask = (const float*)d_in[1];
    const float* Wqkv  = (const float*)d_in[2];
    const float* W1    = (const float*)d_in[3];
    const float* b1    = (const float*)d_in[4];
    const float* W2    = (const float*)d_in[5];
    const float* b2    = (const float*)d_in[6];
    float* out = (float*)d_out;

    float *qkv, *attn, *hid, *seq_t, *wqkv_t, *w1_t, *w2_t;
    cudaGetSymbolAddress((void**)&qkv,    g_qkv);
    cudaGetSymbolAddress((void**)&attn,   g_attn);
    cudaGetSymbolAddress((void**)&hid,    g_hid);
    cudaGetSymbolAddress((void**)&seq_t,  g_seq_t);
    cudaGetSymbolAddress((void**)&wqkv_t, g_wqkv_t);
    cudaGetSymbolAddress((void**)&w1_t,   g_w1_t);
    cudaGetSymbolAddress((void**)&w2_t,   g_w2_t);

    cudaFuncSetAttribute((const void*)tgemm_kernel<0,1>, cudaFuncAttributeMaxDynamicSharedMemorySize, GEMM_SMEM_BYTES);
    cudaFuncSetAttribute((const void*)tgemm_kernel<1,1>, cudaFuncAttributeMaxDynamicSharedMemorySize, GEMM_SMEM_BYTES);
    cudaFuncSetAttribute((const void*)tgemm_kernel<0,0>, cudaFuncAttributeMaxDynamicSharedMemorySize, GEMM_SMEM_BYTES);
    cudaFuncSetAttribute((const void*)attn_kernel,       cudaFuncAttributeMaxDynamicSharedMemorySize, ATTN_SMEM_BYTES);

    // 0) tf32 pre-rounding: seq elementwise; weights transposed to [N][K]
    cvt_tf32_kernel<<<(ROWS * DIM) / 1024, 256>>>(seq, seq_t);
    { dim3 g(3 * DIM / 32, DIM / 32);     cvt_T_kernel<<<g, 256>>>(Wqkv, wqkv_t, DIM, 3 * DIM); }
    { dim3 g(2 * DIM / 32, DIM / 32);     cvt_T_kernel<<<g, 256>>>(W1, w1_t, DIM, 2 * DIM); }
    { dim3 g(DIM / 32, 2 * DIM / 32);     cvt_T_kernel<<<g, 256>>>(W2, w2_t, 2 * DIM, DIM); }

    // 1) QKV projection (output rounded: feeds attention)
    {
        dim3 grid(3 * DIM / 128, ROWS / 128);
        tgemm_kernel<0,1><<<grid, 256, GEMM_SMEM_BYTES>>>(seq_t, wqkv_t, nullptr, qkv, ROWS, 3 * DIM, DIM);
    }
    // 2) Attention (output rounded: feeds FFN1)
    {
        dim3 grid(SEQ / 128, HEADS, BSZ);
        attn_kernel<<<grid, 256, ATTN_SMEM_BYTES>>>(qkv, amask, attn);
    }
    // 3) FFN1 + bias + SiLU (output rounded: feeds FFN2)
    {
        dim3 grid(2 * DIM / 128, ROWS / 128);
        tgemm_kernel<1,1><<<grid, 256, GEMM_SMEM_BYTES>>>(attn, w1_t, b1, hid, ROWS, 2 * DIM, DIM);
    }
    // 4) FFN2 + bias (final output: full fp32)
    {
        dim3 grid(DIM / 128, ROWS / 128);
        tgemm_kernel<0,0><<<grid, 256, GEMM_SMEM_BYTES>>>(hid, w2_t, b2, out, ROWS, DIM, 2 * DIM);
    }
}

// round 12
// speedup vs baseline: 1.0408x; 1.0408x over previous
#include <cuda_runtime.h>
#include <math.h>
#include <stdint.h>

#define DIM   1024
#define HEADS 16
#define BSZ   2
#define SEQ   2048
#define HD    64
#define ROWS  (BSZ*SEQ)   // 4096

// Scratch (device globals; allocation-free)
__device__ float g_qkv[(size_t)ROWS * 3 * DIM];
__device__ float g_attn[(size_t)ROWS * DIM];
__device__ float g_hid[(size_t)ROWS * 2 * DIM];
// tf32-rounded copies of inputs (weights stored TRANSPOSED [N][K])
__device__ float g_seq_t[(size_t)ROWS * DIM];
__device__ float g_wqkv_t[(size_t)DIM * 3 * DIM];
__device__ float g_w1_t[(size_t)DIM * 2 * DIM];
__device__ float g_w2_t[(size_t)2 * DIM * DIM];

// ---------------------------------------------------------------------------
// helpers
// ---------------------------------------------------------------------------
__device__ __forceinline__ void cp16(void* smem_dst, const void* gmem_src) {
    uint32_t d = (uint32_t)__cvta_generic_to_shared(smem_dst);
    asm volatile("cp.async.cg.shared.global [%0], [%1], 16;\n" :: "r"(d), "l"(gmem_src));
}
#define CP_COMMIT() asm volatile("cp.async.commit_group;\n" ::: "memory")
#define CP_WAIT1()  asm volatile("cp.async.wait_group 1;\n" ::: "memory")

__device__ __forceinline__ float f2tf32f(float x) {
    uint32_t r;
    asm("cvt.rna.tf32.f32 %0, %1;" : "=r"(r) : "f"(x));
    return __uint_as_float(r);
}

__device__ __forceinline__ float fexp2(float x) {
    float y;
    asm("ex2.approx.ftz.f32 %0, %1;" : "=f"(y) : "f"(x));
    return y;
}

__device__ __forceinline__ void mma_tf32(float c[4], const uint32_t a[4], const uint32_t* b) {
    asm volatile(
        "mma.sync.aligned.m16n8k8.row.col.f32.tf32.tf32.f32 "
        "{%0,%1,%2,%3}, {%4,%5,%6,%7}, {%8,%9}, {%0,%1,%2,%3};\n"
        : "+f"(c[0]), "+f"(c[1]), "+f"(c[2]), "+f"(c[3])
        : "r"(a[0]), "r"(a[1]), "r"(a[2]), "r"(a[3]), "r"(b[0]), "r"(b[1]));
}

__device__ __forceinline__ void ldsm_x4(uint32_t r[4], uint32_t addr) {
    asm volatile("ldmatrix.sync.aligned.m8n8.x4.shared.b16 {%0,%1,%2,%3}, [%4];"
                 : "=r"(r[0]), "=r"(r[1]), "=r"(r[2]), "=r"(r[3]) : "r"(addr));
}

// ---------------------------------------------------------------------------
// fused tf32 pre-pass (one launch): seq elementwise + 3 weight transposes.
// Block ranges:
//  [0,4096)        seq elementwise (1024 elts per block)
//  [4096,7168)     Wqkv transpose [1024][3072] -> [3072][1024]  (96 x 32 tiles)
//  [7168,9216)     W1   transpose [1024][2048] -> [2048][1024]  (64 x 32 tiles)
//  [9216,11264)    W2   transpose [2048][1024] -> [1024][2048]  (32 x 64 tiles)
// ---------------------------------------------------------------------------
#define CVT_BLOCKS 11264

__device__ __forceinline__ void transpose_tile(
    const float* __restrict__ src, float* __restrict__ dst,
    int K, int N, int n0, int k0)
{
    __shared__ float tile[32][33];
    const int tx = threadIdx.x & 31, ty4 = (threadIdx.x >> 5) * 4;
    #pragma unroll
    for (int i = 0; i < 4; i++)
        tile[ty4 + i][tx] = f2tf32f(src[(size_t)(k0 + ty4 + i) * N + n0 + tx]);
    __syncthreads();
    #pragma unroll
    for (int i = 0; i < 4; i++)
        dst[(size_t)(n0 + ty4 + i) * K + k0 + tx] = tile[tx][ty4 + i];
}

__global__ __launch_bounds__(256)
void cvt_all_kernel(const float* __restrict__ seq, float* __restrict__ seq_t,
                    const float* __restrict__ wqkv, float* __restrict__ wqkv_t,
                    const float* __restrict__ w1, float* __restrict__ w1_t,
                    const float* __restrict__ w2, float* __restrict__ w2_t)
{
    int b = blockIdx.x;
    if (b < 4096) {
        size_t i = (size_t)b * 1024 + (size_t)threadIdx.x * 4;
        float4 v = *(const float4*)(seq + i);
        v.x = f2tf32f(v.x); v.y = f2tf32f(v.y);
        v.z = f2tf32f(v.z); v.w = f2tf32f(v.w);
        *(float4*)(seq_t + i) = v;
    } else if (b < 7168) {
        int m = b - 4096;                    // 96 x 32
        transpose_tile(wqkv, wqkv_t, DIM, 3 * DIM, (m % 96) * 32, (m / 96) * 32);
    } else if (b < 9216) {
        int m = b - 7168;                    // 64 x 32
        transpose_tile(w1, w1_t, DIM, 2 * DIM, (m % 64) * 32, (m / 64) * 32);
    } else {
        int m = b - 9216;                    // 32 x 64
        transpose_tile(w2, w2_t, 2 * DIM, DIM, (m % 32) * 32, (m / 32) * 32);
    }
}

// ---------------------------------------------------------------------------
// tf32 tensor-core GEMM, both operands via ldmatrix.x4.
// A[M][K] row-major; Bt[N][K] row-major (pre-transposed weights).
// ---------------------------------------------------------------------------
#define GS 36
#define G_STAGE (128 * GS)
#define GEMM_SMEM_BYTES (6 * G_STAGE * 4)  // 110592

__device__ __forceinline__ void gemm_load_tile(
    const float* __restrict__ A, const float* __restrict__ Bt,
    int K, int bm, int bn, int k0,
    float* Asb, float* Bsb, int tid)
{
    #pragma unroll
    for (int i = 0; i < 4; i++) {
        int id = tid + i * 256;
        int r = id >> 3, q = (id & 7) * 4;
        cp16(Asb + r * GS + q, A  + (size_t)(bm + r) * K + k0 + q);
        cp16(Bsb + r * GS + q, Bt + (size_t)(bn + r) * K + k0 + q);
    }
}

template<int ACT, int ROUND>
__global__ __launch_bounds__(256, 2)
void tgemm_kernel(const float* __restrict__ A, const float* __restrict__ Bt,
                  const float* __restrict__ bias, float* __restrict__ C,
                  int M, int N, int K)
{
    extern __shared__ float smem[];
    float* As = smem;
    float* Bs = smem + 3 * G_STAGE;

    const int tid  = threadIdx.x;
    const int lane = tid & 31;
    const int wid  = tid >> 5;
    const int gid  = lane >> 2;
    const int tig  = lane & 3;
    const int warp_m = wid & 1;
    const int warp_n = wid >> 1;
    const int bm = blockIdx.y * 128;
    const int bn = blockIdx.x * 128;

    const int lf = lane >> 3, lr = lane & 7;
    const uint32_t As_u32 = (uint32_t)__cvta_generic_to_shared(As);
    const uint32_t Bs_u32 = (uint32_t)__cvta_generic_to_shared(Bs);
    const uint32_t aldm = As_u32 +
        (uint32_t)(((warp_m * 64 + (lf & 1) * 8 + lr) * GS + (lf >> 1) * 4) * 4);
    const uint32_t bldm = Bs_u32 +
        (uint32_t)(((warp_n * 32 + (lf >> 1) * 8 + lr) * GS + (lf & 1) * 4) * 4);

    float acc[4][4][4];
    #pragma unroll
    for (int mt = 0; mt < 4; mt++)
        #pragma unroll
        for (int nt = 0; nt < 4; nt++)
            #pragma unroll
            for (int r = 0; r < 4; r++) acc[mt][nt][r] = 0.f;

    const int T = K / 32;
    gemm_load_tile(A, Bt, K, bm, bn, 0,  As,           Bs,           tid); CP_COMMIT();
    gemm_load_tile(A, Bt, K, bm, bn, 32, As + G_STAGE, Bs + G_STAGE, tid); CP_COMMIT();

    for (int t = 0; t < T; t++) {
        CP_WAIT1();
        __syncthreads();

        int tn = t + 2;
        if (tn < T) {
            gemm_load_tile(A, Bt, K, bm, bn, tn * 32,
                           As + (tn % 3) * G_STAGE, Bs + (tn % 3) * G_STAGE, tid);
        }
        CP_COMMIT();

        const uint32_t a_stage = aldm + (uint32_t)((t % 3) * G_STAGE * 4);
        const uint32_t b_stage = bldm + (uint32_t)((t % 3) * G_STAGE * 4);

        #pragma unroll
        for (int kq = 0; kq < 4; kq++) {
            const int k0s = kq * 8;
            uint32_t af[4][4];
            #pragma unroll
            for (int mt = 0; mt < 4; mt++)
                ldsm_x4(af[mt], a_stage + (uint32_t)((mt * 16 * GS + k0s) * 4));

            uint32_t bf0[4], bf1[4];
            ldsm_x4(bf0, b_stage + (uint32_t)(k0s * 4));
            ldsm_x4(bf1, b_stage + (uint32_t)((16 * GS + k0s) * 4));

            #pragma unroll
            for (int mt = 0; mt < 4; mt++) {
                mma_tf32(acc[mt][0], af[mt], bf0);
                mma_tf32(acc[mt][1], af[mt], bf0 + 2);
                mma_tf32(acc[mt][2], af[mt], bf1);
                mma_tf32(acc[mt][3], af[mt], bf1 + 2);
            }
        }
    }

    #pragma unroll
    for (int mt = 0; mt < 4; mt++) {
        const int r0 = bm + warp_m * 64 + mt * 16 + gid;
        #pragma unroll
        for (int nt = 0; nt < 4; nt++) {
            const int c0 = bn + warp_n * 32 + nt * 8 + tig * 2;
            float b0 = 0.f, b1 = 0.f;
            if (bias) { b0 = bias[c0]; b1 = bias[c0 + 1]; }
            float v0 = acc[mt][nt][0] + b0;
            float v1 = acc[mt][nt][1] + b1;
            float v2 = acc[mt][nt][2] + b0;
            float v3 = acc[mt][nt][3] + b1;
            if (ACT == 1) {
                v0 = v0 / (1.f + __expf(-v0));
                v1 = v1 / (1.f + __expf(-v1));
                v2 = v2 / (1.f + __expf(-v2));
                v3 = v3 / (1.f + __expf(-v3));
            }
            if (ROUND) {
                v0 = f2tf32f(v0); v1 = f2tf32f(v1);
                v2 = f2tf32f(v2); v3 = f2tf32f(v3);
            }
            *(float2*)(C + (size_t)r0 * N + c0)       = make_float2(v0, v1);
            *(float2*)(C + (size_t)(r0 + 8) * N + c0) = make_float2(v2, v3);
        }
    }
}

// ---------------------------------------------------------------------------
// tf32 tensor-core flash attention (R10 structure: K via x4 LDSM, V scalar).
// ---------------------------------------------------------------------------
#define ATS 68
#define KV_STAGE (2 * 64 * ATS)
#define ATTN_SMEM_FLOATS (128 * ATS + 2 * KV_STAGE)
#define ATTN_SMEM_BYTES  (ATTN_SMEM_FLOATS * 4)   // 104448

#define L2E       1.44269504f
#define SCALE_L2E (0.125f * 1.44269504f)

__device__ __forceinline__ void attn_load_kv(
    const float* kbase, const float* vbase, int kv0,
    float* Kst, float* Vst, int tid)
{
    #pragma unroll
    for (int i = 0; i < 4; i++) {
        int c = tid + i * 256;
        int r = c >> 4, q = (c & 15) * 4;
        cp16(Kst + r * ATS + q, kbase + (size_t)(kv0 + r) * (3 * DIM) + q);
        cp16(Vst + r * ATS + q, vbase + (size_t)(kv0 + r) * (3 * DIM) + q);
    }
}

__global__ __launch_bounds__(256, 2)
void attn_kernel(const float* __restrict__ qkv,
                 const float* __restrict__ mask,
                 float* __restrict__ out)
{
    extern __shared__ float smem[];
    float* Ps = smem;                 // 128 x 68 : Q staging, then P
    float* KV = smem + 128 * ATS;

    const int tid  = threadIdx.x;
    const int lane = tid & 31;
    const int w    = tid >> 5;
    const int gid  = lane >> 2;
    const int tig  = lane & 3;
    const int bb = blockIdx.z, h = blockIdx.y;
    const int q0 = blockIdx.x * 128;
    const size_t ldq = 3 * DIM;

    const float* qbase = qkv + (size_t)(bb * SEQ + q0) * ldq + h * HD;
    const float* kbase = qkv + (size_t)(bb * SEQ) * ldq + DIM + h * HD;
    const float* vbase = kbase + DIM;

    const int lf = lane >> 3, lr = lane & 7;
    const uint32_t Ps_u32 = (uint32_t)__cvta_generic_to_shared(Ps);
    const uint32_t KV_u32 = (uint32_t)__cvta_generic_to_shared(KV);
    const uint32_t pldm = Ps_u32 +
        (uint32_t)(((w * 16 + (lf & 1) * 8 + lr) * ATS + (lf >> 1) * 4) * 4);
    const uint32_t kldm_off =
        (uint32_t)((((lf >> 1) * 8 + lr) * ATS + (lf & 1) * 4) * 4);

    #pragma unroll
    for (int i = 0; i < 8; i++) {
        int c = tid + i * 256;
        int r = c >> 4, q = (c & 15) * 4;
        cp16(Ps + r * ATS + q, qbase + (size_t)r * ldq + q);
    }
    attn_load_kv(kbase, vbase, 0, KV, KV + 64 * ATS, tid);
    CP_COMMIT();

    uint32_t qf[8][4];
    float oacc[8][4];
    #pragma unroll
    for (int nt = 0; nt < 8; nt++)
        #pragma unroll
        for (int r = 0; r < 4; r++) oacc[nt][r] = 0.f;
    float mrow0 = -1e30f, mrow1 = -1e30f, lrow0 = 0.f, lrow1 = 0.f;

    const int qrow = w * 16 + gid;
    const int Rg = q0 + qrow;

    const int NT = SEQ / 64;
    for (int t = 0; t < NT; t++) {
        const int cur = t & 1;
        if (t + 1 < NT) {
            float* Kn = KV + ((t + 1) & 1) * KV_STAGE;
            attn_load_kv(kbase, vbase, (t + 1) * 64, Kn, Kn + 64 * ATS, tid);
        }
        CP_COMMIT();
        CP_WAIT1();
        __syncthreads();

        if (t == 0) {
            #pragma unroll
            for (int kt = 0; kt < 8; kt++)
                ldsm_x4(qf[kt], pldm + (uint32_t)(kt * 8 * 4));
        }

        const uint32_t kst_u32 = KV_u32 + (uint32_t)(cur * KV_STAGE * 4) + kldm_off;
        const float* Vst = KV + cur * KV_STAGE + 64 * ATS;
        const int kv0 = t * 64;

        float sa[8][4];
        #pragma unroll
        for (int nt = 0; nt < 8; nt++)
            #pragma unroll
            for (int r = 0; r < 4; r++) sa[nt][r] = 0.f;

        #pragma unroll
        for (int kt = 0; kt < 8; kt++) {
            #pragma unroll
            for (int np = 0; np < 4; np++) {
                uint32_t bfr4[4];
                ldsm_x4(bfr4, kst_u32 + (uint32_t)((np * 16 * ATS + kt * 8) * 4));
                mma_tf32(sa[2 * np],     qf[kt], bfr4);
                mma_tf32(sa[2 * np + 1], qf[kt], bfr4 + 2);
            }
        }

        const float* mp0 = mask + (size_t)Rg * SEQ + kv0 + 2 * tig;
        const float* mp1 = mp0 + 8 * SEQ;
        #pragma unroll
        for (int nt = 0; nt < 8; nt++) {
            float2 mk0 = *(const float2*)(mp0 + nt * 8);
            float2 mk1 = *(const float2*)(mp1 + nt * 8);
            sa[nt][0] = fmaf(sa[nt][0], SCALE_L2E, mk0.x * L2E);
            sa[nt][1] = fmaf(sa[nt][1], SCALE_L2E, mk0.y * L2E);
            sa[nt][2] = fmaf(sa[nt][2], SCALE_L2E, mk1.x * L2E);
            sa[nt][3] = fmaf(sa[nt][3], SCALE_L2E, mk1.y * L2E);
        }

        float mx0 = -1e30f, mx1 = -1e30f;
        #pragma unroll
        for (int nt = 0; nt < 8; nt++) {
            mx0 = fmaxf(mx0, fmaxf(sa[nt][0], sa[nt][1]));
            mx1 = fmaxf(mx1, fmaxf(sa[nt][2], sa[nt][3]));
        }
        mx0 = fmaxf(mx0, __shfl_xor_sync(0xffffffffu, mx0, 1));
        mx0 = fmaxf(mx0, __shfl_xor_sync(0xffffffffu, mx0, 2));
        mx1 = fmaxf(mx1, __shfl_xor_sync(0xffffffffu, mx1, 1));
        mx1 = fmaxf(mx1, __shfl_xor_sync(0xffffffffu, mx1, 2));

        float mn0 = fmaxf(mrow0, mx0);
        float mn1 = fmaxf(mrow1, mx1);
        float alpha0 = fexp2(mrow0 - mn0);
        float alpha1 = fexp2(mrow1 - mn1);
        mrow0 = mn0; mrow1 = mn1;

        float s0a = 0.f, s0b = 0.f, s1a = 0.f, s1b = 0.f;
        #pragma unroll
        for (int nt = 0; nt < 8; nt++) {
            sa[nt][0] = fexp2(sa[nt][0] - mn0);
            sa[nt][1] = fexp2(sa[nt][1] - mn0);
            sa[nt][2] = fexp2(sa[nt][2] - mn1);
            sa[nt][3] = fexp2(sa[nt][3] - mn1);
            if (nt & 1) { s0b += sa[nt][0] + sa[nt][1]; s1b += sa[nt][2] + sa[nt][3]; }
            else        { s0a += sa[nt][0] + sa[nt][1]; s1a += sa[nt][2] + sa[nt][3]; }
        }
        float sum0 = s0a + s0b, sum1 = s1a + s1b;
        sum0 += __shfl_xor_sync(0xffffffffu, sum0, 1);
        sum0 += __shfl_xor_sync(0xffffffffu, sum0, 2);
        sum1 += __shfl_xor_sync(0xffffffffu, sum1, 1);
        sum1 += __shfl_xor_sync(0xffffffffu, sum1, 2);
        lrow0 = lrow0 * alpha0 + sum0;
        lrow1 = lrow1 * alpha1 + sum1;

        #pragma unroll
        for (int nt = 0; nt < 8; nt++) {
            oacc[nt][0] *= alpha0;
            oacc[nt][1] *= alpha0;
            oacc[nt][2] *= alpha1;
            oacc[nt][3] *= alpha1;
        }

        float* pr0 = Ps + qrow * ATS + 2 * tig;
        float* pr1 = pr0 + 8 * ATS;
        #pragma unroll
        for (int nt = 0; nt < 8; nt++) {
            *(float2*)(pr0 + nt * 8) = make_float2(f2tf32f(sa[nt][0]), f2tf32f(sa[nt][1]));
            *(float2*)(pr1 + nt * 8) = make_float2(f2tf32f(sa[nt][2]), f2tf32f(sa[nt][3]));
        }
        __syncwarp();

        #pragma unroll
        for (int kt = 0; kt < 8; kt++) {
            uint32_t pf[4];
            ldsm_x4(pf, pldm + (uint32_t)(kt * 8 * 4));
            #pragma unroll
            for (int nt = 0; nt < 8; nt++) {
                const float* bp = Vst + (kt * 8 + tig) * ATS + nt * 8 + gid;
                uint32_t bfr[2] = { __float_as_uint(bp[0]), __float_as_uint(bp[4 * ATS]) };
                mma_tf32(oacc[nt], pf, bfr);
            }
        }
        __syncthreads();
    }

    float inv0 = 1.f / lrow0, inv1 = 1.f / lrow1;
    float* o0 = out + (size_t)(bb * SEQ + Rg) * DIM + h * HD + 2 * tig;
    float* o1 = o0 + 8 * DIM;
    #pragma unroll
    for (int nt = 0; nt < 8; nt++) {
        *(float2*)(o0 + nt * 8) = make_float2(f2tf32f(oacc[nt][0] * inv0),
                                              f2tf32f(oacc[nt][1] * inv0));
        *(float2*)(o1 + nt * 8) = make_float2(f2tf32f(oacc[nt][2] * inv1),
                                              f2tf32f(oacc[nt][3] * inv1));
    }
}

// ---------------------------------------------------------------------------
// Launch
// ---------------------------------------------------------------------------
extern "C" void kernel_launch(void* const* d_in, const int* in_sizes, int n_in,
                              void* d_out, int out_size)
{
    const float* seq   = (const float*)d_in[0];
    const float* amask = (const float*)d_in[1];
    const float* Wqkv  = (const float*)d_in[2];
    const float* W1    = (const float*)d_in[3];
    const float* b1    = (const float*)d_in[4];
    const float* W2    = (const float*)d_in[5];
    const float* b2    = (const float*)d_in[6];
    float* out = (float*)d_out;

    float *qkv, *attn, *hid, *seq_t, *wqkv_t, *w1_t, *w2_t;
    cudaGetSymbolAddress((void**)&qkv,    g_qkv);
    cudaGetSymbolAddress((void**)&attn,   g_attn);
    cudaGetSymbolAddress((void**)&hid,    g_hid);
    cudaGetSymbolAddress((void**)&seq_t,  g_seq_t);
    cudaGetSymbolAddress((void**)&wqkv_t, g_wqkv_t);
    cudaGetSymbolAddress((void**)&w1_t,   g_w1_t);
    cudaGetSymbolAddress((void**)&w2_t,   g_w2_t);

    cudaFuncSetAttribute((const void*)tgemm_kernel<0,1>, cudaFuncAttributeMaxDynamicSharedMemorySize, GEMM_SMEM_BYTES);
    cudaFuncSetAttribute((const void*)tgemm_kernel<1,1>, cudaFuncAttributeMaxDynamicSharedMemorySize, GEMM_SMEM_BYTES);
    cudaFuncSetAttribute((const void*)tgemm_kernel<0,0>, cudaFuncAttributeMaxDynamicSharedMemorySize, GEMM_SMEM_BYTES);
    cudaFuncSetAttribute((const void*)attn_kernel,       cudaFuncAttributeMaxDynamicSharedMemorySize, ATTN_SMEM_BYTES);

    // 0) fused tf32 pre-pass (seq elementwise + weight transposes), one launch
    cvt_all_kernel<<<CVT_BLOCKS, 256>>>(seq, seq_t, Wqkv, wqkv_t, W1, w1_t, W2, w2_t);

    // 1) QKV projection (output rounded: feeds attention)
    {
        dim3 grid(3 * DIM / 128, ROWS / 128);
        tgemm_kernel<0,1><<<grid, 256, GEMM_SMEM_BYTES>>>(seq_t, wqkv_t, nullptr, qkv, ROWS, 3 * DIM, DIM);
    }
    // 2) Attention (output rounded: feeds FFN1)
    {
        dim3 grid(SEQ / 128, HEADS, BSZ);
        attn_kernel<<<grid, 256, ATTN_SMEM_BYTES>>>(qkv, amask, attn);
    }
    // 3) FFN1 + bias + SiLU (output rounded: feeds FFN2)
    {
        dim3 grid(2 * DIM / 128, ROWS / 128);
        tgemm_kernel<1,1><<<grid, 256, GEMM_SMEM_BYTES>>>(attn, w1_t, b1, hid, ROWS, 2 * DIM, DIM);
    }
    // 4) FFN2 + bias (final output: full fp32)
    {
        dim3 grid(DIM / 128, ROWS / 128);
        tgemm_kernel<0,0><<<grid, 256, GEMM_SMEM_BYTES>>>(hid, w2_t, b2, out, ROWS, DIM, 2 * DIM);
    }
}

// round 14
// speedup vs baseline: 1.1094x; 1.0659x over previous
#include <cuda_runtime.h>
#include <math.h>
#include <stdint.h>

#define DIM   1024
#define HEADS 16
#define BSZ   2
#define SEQ   2048
#define HD    64
#define ROWS  (BSZ*SEQ)   // 4096

// Scratch (device globals; allocation-free)
__device__ float g_qkv[(size_t)ROWS * 3 * DIM];
__device__ float g_attn[(size_t)ROWS * DIM];
__device__ float g_hid[(size_t)ROWS * 2 * DIM];
// tf32-rounded copies of inputs (weights stored TRANSPOSED [N][K])
__device__ float g_seq_t[(size_t)ROWS * DIM];
__device__ float g_wqkv_t[(size_t)DIM * 3 * DIM];
__device__ float g_w1_t[(size_t)DIM * 2 * DIM];
__device__ float g_w2_t[(size_t)2 * DIM * DIM];
// mask pre-scaled by log2(e)
__device__ float g_mask_l2e[(size_t)SEQ * SEQ];

// ---------------------------------------------------------------------------
// helpers
// ---------------------------------------------------------------------------
__device__ __forceinline__ void cp16(void* smem_dst, const void* gmem_src) {
    uint32_t d = (uint32_t)__cvta_generic_to_shared(smem_dst);
    asm volatile("cp.async.cg.shared.global [%0], [%1], 16;\n" :: "r"(d), "l"(gmem_src));
}
#define CP_COMMIT() asm volatile("cp.async.commit_group;\n" ::: "memory")
#define CP_WAIT1()  asm volatile("cp.async.wait_group 1;\n" ::: "memory")

__device__ __forceinline__ float f2tf32f(float x) {
    uint32_t r;
    asm("cvt.rna.tf32.f32 %0, %1;" : "=r"(r) : "f"(x));
    return __uint_as_float(r);
}

__device__ __forceinline__ float fexp2(float x) {
    float y;
    asm("ex2.approx.ftz.f32 %0, %1;" : "=f"(y) : "f"(x));
    return y;
}

__device__ __forceinline__ void mma_tf32(float c[4], const uint32_t a[4], const uint32_t* b) {
    asm volatile(
        "mma.sync.aligned.m16n8k8.row.col.f32.tf32.tf32.f32 "
        "{%0,%1,%2,%3}, {%4,%5,%6,%7}, {%8,%9}, {%0,%1,%2,%3};\n"
        : "+f"(c[0]), "+f"(c[1]), "+f"(c[2]), "+f"(c[3])
        : "r"(a[0]), "r"(a[1]), "r"(a[2]), "r"(a[3]), "r"(b[0]), "r"(b[1]));
}

__device__ __forceinline__ void ldsm_x4(uint32_t r[4], uint32_t addr) {
    asm volatile("ldmatrix.sync.aligned.m8n8.x4.shared.b16 {%0,%1,%2,%3}, [%4];"
                 : "=r"(r[0]), "=r"(r[1]), "=r"(r[2]), "=r"(r[3]) : "r"(addr));
}

// ---------------------------------------------------------------------------
// fused tf32 pre-pass (one launch):
//  [0,4096)        seq elementwise tf32 round
//  [4096,7168)     Wqkv transpose  (96 x 32 tiles)
//  [7168,9216)     W1   transpose  (64 x 32 tiles)
//  [9216,11264)    W2   transpose  (32 x 64 tiles)
//  [11264,15360)   mask * log2(e)
// ---------------------------------------------------------------------------
#define CVT_BLOCKS 15360
#define L2E       1.44269504f
#define SCALE_L2E (0.125f * 1.44269504f)

__device__ __forceinline__ void transpose_tile(
    const float* __restrict__ src, float* __restrict__ dst,
    int K, int N, int n0, int k0)
{
    __shared__ float tile[32][33];
    const int tx = threadIdx.x & 31, ty4 = (threadIdx.x >> 5) * 4;
    #pragma unroll
    for (int i = 0; i < 4; i++)
        tile[ty4 + i][tx] = f2tf32f(src[(size_t)(k0 + ty4 + i) * N + n0 + tx]);
    __syncthreads();
    #pragma unroll
    for (int i = 0; i < 4; i++)
        dst[(size_t)(n0 + ty4 + i) * K + k0 + tx] = tile[tx][ty4 + i];
}

__global__ __launch_bounds__(256)
void cvt_all_kernel(const float* __restrict__ seq, float* __restrict__ seq_t,
                    const float* __restrict__ wqkv, float* __restrict__ wqkv_t,
                    const float* __restrict__ w1, float* __restrict__ w1_t,
                    const float* __restrict__ w2, float* __restrict__ w2_t,
                    const float* __restrict__ mask, float* __restrict__ mask_l2e)
{
    int b = blockIdx.x;
    if (b < 4096) {
        size_t i = (size_t)b * 1024 + (size_t)threadIdx.x * 4;
        float4 v = *(const float4*)(seq + i);
        v.x = f2tf32f(v.x); v.y = f2tf32f(v.y);
        v.z = f2tf32f(v.z); v.w = f2tf32f(v.w);
        *(float4*)(seq_t + i) = v;
    } else if (b < 7168) {
        int m = b - 4096;
        transpose_tile(wqkv, wqkv_t, DIM, 3 * DIM, (m % 96) * 32, (m / 96) * 32);
    } else if (b < 9216) {
        int m = b - 7168;
        transpose_tile(w1, w1_t, DIM, 2 * DIM, (m % 64) * 32, (m / 64) * 32);
    } else if (b < 11264) {
        int m = b - 9216;
        transpose_tile(w2, w2_t, 2 * DIM, DIM, (m % 32) * 32, (m / 32) * 32);
    } else {
        size_t i = (size_t)(b - 11264) * 1024 + (size_t)threadIdx.x * 4;
        float4 v = *(const float4*)(mask + i);
        v.x *= L2E; v.y *= L2E; v.z *= L2E; v.w *= L2E;
        *(float4*)(mask_l2e + i) = v;
    }
}

// ---------------------------------------------------------------------------
// tf32 tensor-core GEMM (R12): both operands via ldmatrix.x4.
// A[M][K] row-major; Bt[N][K] row-major (pre-transposed weights).
// ---------------------------------------------------------------------------
#define GS 36
#define G_STAGE (128 * GS)
#define GEMM_SMEM_BYTES (6 * G_STAGE * 4)  // 110592

__device__ __forceinline__ void gemm_load_tile(
    const float* __restrict__ A, const float* __restrict__ Bt,
    int K, int bm, int bn, int k0,
    float* Asb, float* Bsb, int tid)
{
    #pragma unroll
    for (int i = 0; i < 4; i++) {
        int id = tid + i * 256;
        int r = id >> 3, q = (id & 7) * 4;
        cp16(Asb + r * GS + q, A  + (size_t)(bm + r) * K + k0 + q);
        cp16(Bsb + r * GS + q, Bt + (size_t)(bn + r) * K + k0 + q);
    }
}

template<int ACT, int ROUND>
__global__ __launch_bounds__(256, 2)
void tgemm_kernel(const float* __restrict__ A, const float* __restrict__ Bt,
                  const float* __restrict__ bias, float* __restrict__ C,
                  int M, int N, int K)
{
    extern __shared__ float smem[];
    float* As = smem;
    float* Bs = smem + 3 * G_STAGE;

    const int tid  = threadIdx.x;
    const int lane = tid & 31;
    const int wid  = tid >> 5;
    const int gid  = lane >> 2;
    const int tig  = lane & 3;
    const int warp_m = wid & 1;
    const int warp_n = wid >> 1;
    const int bm = blockIdx.y * 128;
    const int bn = blockIdx.x * 128;

    const int lf = lane >> 3, lr = lane & 7;
    const uint32_t As_u32 = (uint32_t)__cvta_generic_to_shared(As);
    const uint32_t Bs_u32 = (uint32_t)__cvta_generic_to_shared(Bs);
    const uint32_t aldm = As_u32 +
        (uint32_t)(((warp_m * 64 + (lf & 1) * 8 + lr) * GS + (lf >> 1) * 4) * 4);
    const uint32_t bldm = Bs_u32 +
        (uint32_t)(((warp_n * 32 + (lf >> 1) * 8 + lr) * GS + (lf & 1) * 4) * 4);

    float acc[4][4][4];
    #pragma unroll
    for (int mt = 0; mt < 4; mt++)
        #pragma unroll
        for (int nt = 0; nt < 4; nt++)
            #pragma unroll
            for (int r = 0; r < 4; r++) acc[mt][nt][r] = 0.f;

    const int T = K / 32;
    gemm_load_tile(A, Bt, K, bm, bn, 0,  As,           Bs,           tid); CP_COMMIT();
    gemm_load_tile(A, Bt, K, bm, bn, 32, As + G_STAGE, Bs + G_STAGE, tid); CP_COMMIT();

    for (int t = 0; t < T; t++) {
        CP_WAIT1();
        __syncthreads();

        int tn = t + 2;
        if (tn < T) {
            gemm_load_tile(A, Bt, K, bm, bn, tn * 32,
                           As + (tn % 3) * G_STAGE, Bs + (tn % 3) * G_STAGE, tid);
        }
        CP_COMMIT();

        const uint32_t a_stage = aldm + (uint32_t)((t % 3) * G_STAGE * 4);
        const uint32_t b_stage = bldm + (uint32_t)((t % 3) * G_STAGE * 4);

        #pragma unroll
        for (int kq = 0; kq < 4; kq++) {
            const int k0s = kq * 8;
            uint32_t af[4][4];
            #pragma unroll
            for (int mt = 0; mt < 4; mt++)
                ldsm_x4(af[mt], a_stage + (uint32_t)((mt * 16 * GS + k0s) * 4));

            uint32_t bf0[4], bf1[4];
            ldsm_x4(bf0, b_stage + (uint32_t)(k0s * 4));
            ldsm_x4(bf1, b_stage + (uint32_t)((16 * GS + k0s) * 4));

            #pragma unroll
            for (int mt = 0; mt < 4; mt++) {
                mma_tf32(acc[mt][0], af[mt], bf0);
                mma_tf32(acc[mt][1], af[mt], bf0 + 2);
                mma_tf32(acc[mt][2], af[mt], bf1);
                mma_tf32(acc[mt][3], af[mt], bf1 + 2);
            }
        }
    }

    #pragma unroll
    for (int mt = 0; mt < 4; mt++) {
        const int r0 = bm + warp_m * 64 + mt * 16 + gid;
        #pragma unroll
        for (int nt = 0; nt < 4; nt++) {
            const int c0 = bn + warp_n * 32 + nt * 8 + tig * 2;
            float b0 = 0.f, b1 = 0.f;
            if (bias) { b0 = bias[c0]; b1 = bias[c0 + 1]; }
            float v0 = acc[mt][nt][0] + b0;
            float v1 = acc[mt][nt][1] + b1;
            float v2 = acc[mt][nt][2] + b0;
            float v3 = acc[mt][nt][3] + b1;
            if (ACT == 1) {
                v0 = v0 / (1.f + __expf(-v0));
                v1 = v1 / (1.f + __expf(-v1));
                v2 = v2 / (1.f + __expf(-v2));
                v3 = v3 / (1.f + __expf(-v3));
            }
            if (ROUND) {
                v0 = f2tf32f(v0); v1 = f2tf32f(v1);
                v2 = f2tf32f(v2); v3 = f2tf32f(v3);
            }
            *(float2*)(C + (size_t)r0 * N + c0)       = make_float2(v0, v1);
            *(float2*)(C + (size_t)(r0 + 8) * N + c0) = make_float2(v2, v3);
        }
    }
}

// ---------------------------------------------------------------------------
// tf32 tensor-core flash attention.
// K stride 68 (ldmatrix-friendly); V stride 72 (conflict-free scalar B loads).
// Mask pre-scaled by log2(e) in the pre-pass.
// ---------------------------------------------------------------------------
#define ATS 68
#define VTS 72
#define KV_STAGE (64 * ATS + 64 * VTS)     // 8960 floats per stage
#define ATTN_SMEM_FLOATS (128 * ATS + 2 * KV_STAGE)
#define ATTN_SMEM_BYTES  (ATTN_SMEM_FLOATS * 4)   // 106496

__device__ __forceinline__ void attn_load_kv(
    const float* kbase, const float* vbase, int kv0,
    float* Kst, float* Vst, int tid)
{
    #pragma unroll
    for (int i = 0; i < 4; i++) {
        int c = tid + i * 256;
        int r = c >> 4, q = (c & 15) * 4;
        cp16(Kst + r * ATS + q, kbase + (size_t)(kv0 + r) * (3 * DIM) + q);
        cp16(Vst + r * VTS + q, vbase + (size_t)(kv0 + r) * (3 * DIM) + q);
    }
}

__global__ __launch_bounds__(256, 2)
void attn_kernel(const float* __restrict__ qkv,
                 const float* __restrict__ mask,   // pre-scaled by log2(e)
                 float* __restrict__ out)
{
    extern __shared__ float smemf[];
    float* Ps = smemf;                // 128 x 68 : Q staging, then P
    float* KV = smemf + 128 * ATS;

    const int tid  = threadIdx.x;
    const int lane = tid & 31;
    const int w    = tid >> 5;
    const int gid  = lane >> 2;
    const int tig  = lane & 3;
    const int bb = blockIdx.z, h = blockIdx.y;
    const int q0 = blockIdx.x * 128;
    const size_t ldq = 3 * DIM;

    const float* qbase = qkv + (size_t)(bb * SEQ + q0) * ldq + h * HD;
    const float* kbase = qkv + (size_t)(bb * SEQ) * ldq + DIM + h * HD;
    const float* vbase = kbase + DIM;

    const int lf = lane >> 3, lr = lane & 7;
    const uint32_t Ps_u32 = (uint32_t)__cvta_generic_to_shared(Ps);
    const uint32_t KV_u32 = (uint32_t)__cvta_generic_to_shared(KV);
    const uint32_t pldm = Ps_u32 +
        (uint32_t)(((w * 16 + (lf & 1) * 8 + lr) * ATS + (lf >> 1) * 4) * 4);
    const uint32_t kldm_off =
        (uint32_t)((((lf >> 1) * 8 + lr) * ATS + (lf & 1) * 4) * 4);

    #pragma unroll
    for (int i = 0; i < 8; i++) {
        int c = tid + i * 256;
        int r = c >> 4, q = (c & 15) * 4;
        cp16(Ps + r * ATS + q, qbase + (size_t)r * ldq + q);
    }
    attn_load_kv(kbase, vbase, 0, KV, KV + 64 * ATS, tid);
    CP_COMMIT();

    uint32_t qf[8][4];
    float oacc[8][4];
    #pragma unroll
    for (int nt = 0; nt < 8; nt++)
        #pragma unroll
        for (int r = 0; r < 4; r++) oacc[nt][r] = 0.f;
    float mrow0 = -1e30f, mrow1 = -1e30f, lrow0 = 0.f, lrow1 = 0.f;

    const int qrow = w * 16 + gid;
    const int Rg = q0 + qrow;

    const int NT = SEQ / 64;
    for (int t = 0; t < NT; t++) {
        const int cur = t & 1;
        if (t + 1 < NT) {
            float* Kn = KV + ((t + 1) & 1) * KV_STAGE;
            attn_load_kv(kbase, vbase, (t + 1) * 64, Kn, Kn + 64 * ATS, tid);
        }
        CP_COMMIT();
        CP_WAIT1();
        __syncthreads();

        if (t == 0) {
            #pragma unroll
            for (int kt = 0; kt < 8; kt++)
                ldsm_x4(qf[kt], pldm + (uint32_t)(kt * 8 * 4));
        }

        const uint32_t kst_u32 = KV_u32 + (uint32_t)(cur * KV_STAGE * 4) + kldm_off;
        const float* Vst = KV + cur * KV_STAGE + 64 * ATS;
        const int kv0 = t * 64;

        float sa[8][4];
        #pragma unroll
        for (int nt = 0; nt < 8; nt++)
            #pragma unroll
            for (int r = 0; r < 4; r++) sa[nt][r] = 0.f;

        #pragma unroll
        for (int kt = 0; kt < 8; kt++) {
            #pragma unroll
            for (int np = 0; np < 4; np++) {
                uint32_t bfr4[4];
                ldsm_x4(bfr4, kst_u32 + (uint32_t)((np * 16 * ATS + kt * 8) * 4));
                mma_tf32(sa[2 * np],     qf[kt], bfr4);
                mma_tf32(sa[2 * np + 1], qf[kt], bfr4 + 2);
            }
        }

        const float* mp0 = mask + (size_t)Rg * SEQ + kv0 + 2 * tig;
        const float* mp1 = mp0 + 8 * SEQ;
        #pragma unroll
        for (int nt = 0; nt < 8; nt++) {
            float2 mk0 = *(const float2*)(mp0 + nt * 8);
            float2 mk1 = *(const float2*)(mp1 + nt * 8);
            sa[nt][0] = fmaf(sa[nt][0], SCALE_L2E, mk0.x);
            sa[nt][1] = fmaf(sa[nt][1], SCALE_L2E, mk0.y);
            sa[nt][2] = fmaf(sa[nt][2], SCALE_L2E, mk1.x);
            sa[nt][3] = fmaf(sa[nt][3], SCALE_L2E, mk1.y);
        }

        float mx0 = -1e30f, mx1 = -1e30f;
        #pragma unroll
        for (int nt = 0; nt < 8; nt++) {
            mx0 = fmaxf(mx0, fmaxf(sa[nt][0], sa[nt][1]));
            mx1 = fmaxf(mx1, fmaxf(sa[nt][2], sa[nt][3]));
        }
        mx0 = fmaxf(mx0, __shfl_xor_sync(0xffffffffu, mx0, 1));
        mx0 = fmaxf(mx0, __shfl_xor_sync(0xffffffffu, mx0, 2));
        mx1 = fmaxf(mx1, __shfl_xor_sync(0xffffffffu, mx1, 1));
        mx1 = fmaxf(mx1, __shfl_xor_sync(0xffffffffu, mx1, 2));

        float mn0 = fmaxf(mrow0, mx0);
        float mn1 = fmaxf(mrow1, mx1);
        float alpha0 = fexp2(mrow0 - mn0);
        float alpha1 = fexp2(mrow1 - mn1);
        mrow0 = mn0; mrow1 = mn1;

        float s0a = 0.f, s0b = 0.f, s1a = 0.f, s1b = 0.f;
        #pragma unroll
        for (int nt = 0; nt < 8; nt++) {
            sa[nt][0] = fexp2(sa[nt][0] - mn0);
            sa[nt][1] = fexp2(sa[nt][1] - mn0);
            sa[nt][2] = fexp2(sa[nt][2] - mn1);
            sa[nt][3] = fexp2(sa[nt][3] - mn1);
            if (nt & 1) { s0b += sa[nt][0] + sa[nt][1]; s1b += sa[nt][2] + sa[nt][3]; }
            else        { s0a += sa[nt][0] + sa[nt][1]; s1a += sa[nt][2] + sa[nt][3]; }
        }
        float sum0 = s0a + s0b, sum1 = s1a + s1b;
        sum0 += __shfl_xor_sync(0xffffffffu, sum0, 1);
        sum0 += __shfl_xor_sync(0xffffffffu, sum0, 2);
        sum1 += __shfl_xor_sync(0xffffffffu, sum1, 1);
        sum1 += __shfl_xor_sync(0xffffffffu, sum1, 2);
        lrow0 = lrow0 * alpha0 + sum0;
        lrow1 = lrow1 * alpha1 + sum1;

        #pragma unroll
        for (int nt = 0; nt < 8; nt++) {
            oacc[nt][0] *= alpha0;
            oacc[nt][1] *= alpha0;
            oacc[nt][2] *= alpha1;
            oacc[nt][3] *= alpha1;
        }

        float* pr0 = Ps + qrow * ATS + 2 * tig;
        float* pr1 = pr0 + 8 * ATS;
        #pragma unroll
        for (int nt = 0; nt < 8; nt++) {
            *(float2*)(pr0 + nt * 8) = make_float2(f2tf32f(sa[nt][0]), f2tf32f(sa[nt][1]));
            *(float2*)(pr1 + nt * 8) = make_float2(f2tf32f(sa[nt][2]), f2tf32f(sa[nt][3]));
        }
        __syncwarp();

        #pragma unroll
        for (int kt = 0; kt < 8; kt++) {
            uint32_t pf[4];
            ldsm_x4(pf, pldm + (uint32_t)(kt * 8 * 4));
            #pragma unroll
            for (int nt = 0; nt < 8; nt++) {
                const float* bp = Vst + (kt * 8 + tig) * VTS + nt * 8 + gid;
                uint32_t bfr[2] = { __float_as_uint(bp[0]), __float_as_uint(bp[4 * VTS]) };
                mma_tf32(oacc[nt], pf, bfr);
            }
        }
        __syncthreads();
    }

    float inv0 = 1.f / lrow0, inv1 = 1.f / lrow1;
    float* o0 = out + (size_t)(bb * SEQ + Rg) * DIM + h * HD + 2 * tig;
    float* o1 = o0 + 8 * DIM;
    #pragma unroll
    for (int nt = 0; nt < 8; nt++) {
        *(float2*)(o0 + nt * 8) = make_float2(f2tf32f(oacc[nt][0] * inv0),
                                              f2tf32f(oacc[nt][1] * inv0));
        *(float2*)(o1 + nt * 8) = make_float2(f2tf32f(oacc[nt][2] * inv1),
                                              f2tf32f(oacc[nt][3] * inv1));
    }
}

// ---------------------------------------------------------------------------
// Launch
// ---------------------------------------------------------------------------
extern "C" void kernel_launch(void* const* d_in, const int* in_sizes, int n_in,
                              void* d_out, int out_size)
{
    const float* seq   = (const float*)d_in[0];
    const float* amask = (const float*)d_in[1];
    const float* Wqkv  = (const float*)d_in[2];
    const float* W1    = (const float*)d_in[3];
    const float* b1    = (const float*)d_in[4];
    const float* W2    = (const float*)d_in[5];
    const float* b2    = (const float*)d_in[6];
    float* out = (float*)d_out;

    float *qkv, *attn, *hid, *seq_t, *wqkv_t, *w1_t, *w2_t, *mask_l2e;
    cudaGetSymbolAddress((void**)&qkv,      g_qkv);
    cudaGetSymbolAddress((void**)&attn,     g_attn);
    cudaGetSymbolAddress((void**)&hid,      g_hid);
    cudaGetSymbolAddress((void**)&seq_t,    g_seq_t);
    cudaGetSymbolAddress((void**)&wqkv_t,   g_wqkv_t);
    cudaGetSymbolAddress((void**)&w1_t,     g_w1_t);
    cudaGetSymbolAddress((void**)&w2_t,     g_w2_t);
    cudaGetSymbolAddress((void**)&mask_l2e, g_mask_l2e);

    cudaFuncSetAttribute((const void*)tgemm_kernel<0,1>, cudaFuncAttributeMaxDynamicSharedMemorySize, GEMM_SMEM_BYTES);
    cudaFuncSetAttribute((const void*)tgemm_kernel<1,1>, cudaFuncAttributeMaxDynamicSharedMemorySize, GEMM_SMEM_BYTES);
    cudaFuncSetAttribute((const void*)tgemm_kernel<0,0>, cudaFuncAttributeMaxDynamicSharedMemorySize, GEMM_SMEM_BYTES);
    cudaFuncSetAttribute((const void*)attn_kernel,       cudaFuncAttributeMaxDynamicSharedMemorySize, ATTN_SMEM_BYTES);

    // 0) fused pre-pass: tf32 rounding, weight transposes, mask*log2e
    cvt_all_kernel<<<CVT_BLOCKS, 256>>>(seq, seq_t, Wqkv, wqkv_t, W1, w1_t, W2, w2_t,
                                        amask, mask_l2e);

    // 1) QKV projection (output rounded: feeds attention)
    {
        dim3 grid(3 * DIM / 128, ROWS / 128);
        tgemm_kernel<0,1><<<grid, 256, GEMM_SMEM_BYTES>>>(seq_t, wqkv_t, nullptr, qkv, ROWS, 3 * DIM, DIM);
    }
    // 2) Attention (output rounded: feeds FFN1)
    {
        dim3 grid(SEQ / 128, HEADS, BSZ);
        attn_kernel<<<grid, 256, ATTN_SMEM_BYTES>>>(qkv, mask_l2e, attn);
    }
    // 3) FFN1 + bias + SiLU (output rounded: feeds FFN2)
    {
        dim3 grid(2 * DIM / 128, ROWS / 128);
        tgemm_kernel<1,1><<<grid, 256, GEMM_SMEM_BYTES>>>(attn, w1_t, b1, hid, ROWS, 2 * DIM, DIM);
    }
    // 4) FFN2 + bias (final output: full fp32)
    {
        dim3 grid(DIM / 128, ROWS / 128);
        tgemm_kernel<0,0><<<grid, 256, GEMM_SMEM_BYTES>>>(hid, w2_t, b2, out, ROWS, DIM, 2 * DIM);
    }
}